// round 3
// baseline (speedup 1.0000x reference)
#include <cuda_runtime.h>
#include <cstdint>

// Problem shape (fixed by setup_inputs)
#define BB 8
#define NN 2000
#define EE 20
#define HH 128
#define ROWS (BB * NN)       // 16000 node rows

typedef unsigned long long ull;

// Scratch (static device arrays — no runtime allocation)
__device__ float g_Ux[ROWS * HH];
__device__ float g_Vx[ROWS * HH];
__device__ float g_WeT[HH * HH];   // We transposed: [h][k]

// ---------------------------------------------------------------------------
// Packed fp32x2 helpers (Blackwell sm_103a)
// ---------------------------------------------------------------------------
__device__ __forceinline__ ull ffma2(ull a, ull b, ull c) {
    ull d;
    asm("fma.rn.f32x2 %0, %1, %2, %3;" : "=l"(d) : "l"(a), "l"(b), "l"(c));
    return d;
}
__device__ __forceinline__ ull splat2(float f) {
    ull d; unsigned u = __float_as_uint(f);
    asm("mov.b64 %0, {%1, %1};" : "=l"(d) : "r"(u));
    return d;
}
__device__ __forceinline__ void unpack2(ull v, float& lo, float& hi) {
    unsigned a, b;
    asm("mov.b64 {%0, %1}, %2;" : "=r"(a), "=r"(b) : "l"(v));
    lo = __uint_as_float(a); hi = __uint_as_float(b);
}
__device__ __forceinline__ void lds_v2u64(ull& a, ull& b, const float* p) {
    asm volatile("ld.shared.v2.u64 {%0, %1}, [%2];"
                 : "=l"(a), "=l"(b)
                 : "l"(__cvta_generic_to_shared(p)));
}

// ---------------------------------------------------------------------------
// transpose_We: g_WeT[h][k] = We[k][h]   (64 KB one-shot, reads strided but tiny)
// ---------------------------------------------------------------------------
__global__ void transpose_We(const float* __restrict__ We) {
    int h = blockIdx.x, k = threadIdx.x;
    g_WeT[h * HH + k] = We[k * HH + h];
}

// ---------------------------------------------------------------------------
// linear_dual: computes BOTH Ux = x@Wu+bu and Vx = x@Wv+bv in one pass.
// Block: 256 threads, 32 rows. Thread tile: 4 rows x 4 cols (2 f32x2 pairs).
// x stored pre-splatted (x,x) in smem; W column pairs load natively packed.
// ---------------------------------------------------------------------------
__global__ __launch_bounds__(256) void linear_dual(
    const float* __restrict__ x,
    const float* __restrict__ Wu, const float* __restrict__ bu,
    const float* __restrict__ Wv, const float* __restrict__ bv)
{
    __shared__ __align__(16) ull x_dup[32 * HH];  // 32 KB, each elem = (x,x)

    const int t    = threadIdx.x;    // 0..255
    const int hq   = t & 31;         // cols hq*4 .. hq*4+3
    const int rg   = t >> 5;         // rows rg*4 .. rg*4+3
    const int row0 = blockIdx.x * 32;

    // Cooperative load of the 32x128 x tile, splat each value into a pair
    {
        const float4* xg = (const float4*)(x + (size_t)row0 * HH);
        #pragma unroll
        for (int i = 0; i < 4; i++) {
            float4 v = xg[t + i * 256];
            int base = (t + i * 256) * 4;
            x_dup[base + 0] = splat2(v.x);
            x_dup[base + 1] = splat2(v.y);
            x_dup[base + 2] = splat2(v.z);
            x_dup[base + 3] = splat2(v.w);
        }
    }
    __syncthreads();

    ull accU[4][2], accV[4][2];
    #pragma unroll
    for (int r = 0; r < 4; r++) {
        accU[r][0] = accU[r][1] = 0ull;
        accV[r][0] = accV[r][1] = 0ull;
    }

    #pragma unroll 4
    for (int k = 0; k < HH; k++) {
        // W[k][4hq .. 4hq+3] as two packed f32x2 (16B aligned)
        const ulonglong2 wu2 = *(const ulonglong2*)(Wu + (size_t)k * HH + hq * 4);
        const ulonglong2 wv2 = *(const ulonglong2*)(Wv + (size_t)k * HH + hq * 4);
        #pragma unroll
        for (int r = 0; r < 4; r++) {
            const ull xv = x_dup[(rg * 4 + r) * HH + k];  // warp-uniform broadcast
            accU[r][0] = ffma2(xv, wu2.x, accU[r][0]);
            accU[r][1] = ffma2(xv, wu2.y, accU[r][1]);
            accV[r][0] = ffma2(xv, wv2.x, accV[r][0]);
            accV[r][1] = ffma2(xv, wv2.y, accV[r][1]);
        }
    }

    const float4 bu4 = *(const float4*)(bu + hq * 4);
    const float4 bv4 = *(const float4*)(bv + hq * 4);
    #pragma unroll
    for (int r = 0; r < 4; r++) {
        const size_t o = (size_t)(row0 + rg * 4 + r) * HH + hq * 4;
        float a0, a1, a2, a3;
        unpack2(accU[r][0], a0, a1); unpack2(accU[r][1], a2, a3);
        *(float4*)(g_Ux + o) = make_float4(a0 + bu4.x, a1 + bu4.y, a2 + bu4.z, a3 + bu4.w);
        unpack2(accV[r][0], a0, a1); unpack2(accV[r][1], a2, a3);
        *(float4*)(g_Vx + o) = make_float4(a0 + bv4.x, a1 + bv4.y, a2 + bv4.z, a3 + bv4.w);
    }
}

// ---------------------------------------------------------------------------
// fused_kernel: one CTA per node, 128 threads (thread = channel h).
// Edge dimension packed 2-wide into f32x2; edge tile transposed in smem so a
// single ld.shared.v2.u64 yields 4 edge values as two packed operands.
// Then softmax over E per thread + gather-weighted sum + Ux add.
// (be is dropped: softmax over E is invariant to per-(n,h) shifts.)
// ---------------------------------------------------------------------------
__global__ __launch_bounds__(128) void fused_kernel(
    const float* __restrict__ e,
    const int* __restrict__ edge_index,
    float* __restrict__ out)
{
    __shared__ __align__(16) float e_T[HH * EE];  // [k][i], rows 80B (16B-mult)
    __shared__ int idx_s[EE];

    const int t   = threadIdx.x;   // channel h AND owned k-column for transpose
    const int row = blockIdx.x;    // 0..15999
    const int b   = row / NN;

    // Transposed load: thread t owns k=t; reads are coalesced across t per i.
    const float* eg = e + (size_t)row * EE * HH;
    #pragma unroll
    for (int i = 0; i < EE; i++)
        e_T[t * EE + i] = eg[i * HH + t];

    if (t < EE) idx_s[t] = edge_index[(size_t)row * EE + t];
    __syncthreads();

    ull ve2[10];
    #pragma unroll
    for (int i = 0; i < 10; i++) ve2[i] = 0ull;

    const float4* wt = (const float4*)(g_WeT + (size_t)t * HH);
    #pragma unroll 2
    for (int kq = 0; kq < 32; kq++) {
        const float4 w4 = wt[kq];                   // We[k..k+3][t], 1 LDG.128
        ull w2[4];
        w2[0] = splat2(w4.x); w2[1] = splat2(w4.y);
        w2[2] = splat2(w4.z); w2[3] = splat2(w4.w);
        #pragma unroll
        for (int j = 0; j < 4; j++) {
            const float* base = e_T + (kq * 4 + j) * EE;
            #pragma unroll
            for (int ip = 0; ip < 5; ip++) {
                ull a, c;
                lds_v2u64(a, c, base + ip * 4);     // edges 4ip..4ip+3 at this k
                ve2[2 * ip]     = ffma2(a, w2[j], ve2[2 * ip]);
                ve2[2 * ip + 1] = ffma2(c, w2[j], ve2[2 * ip + 1]);
            }
        }
    }

    // Unpack logits (edge order preserved: ve2[2ip]=(4ip,4ip+1), ve2[2ip+1]=(4ip+2,4ip+3))
    float v[EE];
    #pragma unroll
    for (int ip = 0; ip < 5; ip++) {
        unpack2(ve2[2 * ip],     v[4 * ip],     v[4 * ip + 1]);
        unpack2(ve2[2 * ip + 1], v[4 * ip + 2], v[4 * ip + 3]);
    }

    // Per-thread softmax over E
    float m = v[0];
    #pragma unroll
    for (int i = 1; i < EE; i++) m = fmaxf(m, v[i]);
    float s = 0.f;
    #pragma unroll
    for (int i = 0; i < EE; i++) { v[i] = __expf(v[i] - m); s += v[i]; }
    const float inv = 1.f / s;

    // Gather + weighted sum (Vx is 8.2 MB — L2 resident)
    float acc = 0.f;
    #pragma unroll
    for (int i = 0; i < EE; i++)
        acc += v[i] * g_Vx[((size_t)b * NN + idx_s[i]) * HH + t];

    out[(size_t)row * HH + t] = g_Ux[(size_t)row * HH + t] + acc * inv;
}

// ---------------------------------------------------------------------------
// Launch. Inputs: x, e, Wu, bu, Wv, bv, We, be, edge_index, n_edges
// ---------------------------------------------------------------------------
extern "C" void kernel_launch(void* const* d_in, const int* in_sizes, int n_in,
                              void* d_out, int out_size)
{
    const float* x   = (const float*)d_in[0];
    const float* e   = (const float*)d_in[1];
    const float* Wu  = (const float*)d_in[2];
    const float* bu  = (const float*)d_in[3];
    const float* Wv  = (const float*)d_in[4];
    const float* bv  = (const float*)d_in[5];
    const float* We  = (const float*)d_in[6];
    // be (d_in[7]) irrelevant: softmax over E is shift-invariant per (n,h).
    const int* edge_index = (const int*)d_in[8];
    float* out = (float*)d_out;

    (void)in_sizes; (void)n_in; (void)out_size;

    transpose_We<<<HH, HH>>>(We);
    linear_dual<<<ROWS / 32, 256>>>(x, Wu, bu, Wv, bv);
    fused_kernel<<<ROWS, 128>>>(e, edge_index, out);
}

// round 7
// speedup vs baseline: 2.9756x; 2.9756x over previous
#include <cuda_runtime.h>
#include <cstdint>

// Problem shape (fixed by setup_inputs)
#define BB 8
#define NN 2000
#define EE 20
#define HH 128
#define ROWS (BB * NN)        // 16000 node rows
#define NODES_PER_CTA 8
#define NTILE (NODES_PER_CTA * EE)   // 160 edge rows per CTA (MMA N)

// padded smem strides (in 4B words)
#define AS 132     // A: [128][128] tf32, stride 132 -> conflict-free frag loads
#define BS 132     // B: [160][128] tf32
#define DS 164     // D: [128][160] f32, stride 164 (16B multiple)

// smem layout (bytes)
#define SM_IDX   0
#define SM_A     1024
#define A_BYTES  (HH * AS * 4)            // 67584
#define SM_B     (SM_A + A_BYTES)         // 68608 (16B aligned)
#define B_BYTES  (NTILE * BS * 4)         // 84480
#define SM_TOTAL (SM_B + B_BYTES)         // 153088  (D reuses B region: 128*164*4=83968)

// Scratch (static device arrays — no runtime allocation)
__device__ float g_Ux[ROWS * HH];
__device__ float g_Vx[ROWS * HH];
__device__ float g_WeT[HH * HH];   // A operand: A[m=h][k] = We[k][h]

__device__ __forceinline__ uint32_t to_tf32(float f) {
    uint32_t r; asm("cvt.rna.tf32.f32 %0, %1;" : "=r"(r) : "f"(f)); return r;
}

// m16n8k8 tf32 warp MMA (family-portable PTX, sm_80+; no tcgen05 on this target)
__device__ __forceinline__ void mma_tf32(float d[4], const uint32_t a[4],
                                         const uint32_t b[2]) {
    asm volatile(
        "mma.sync.aligned.m16n8k8.row.col.f32.tf32.tf32.f32 "
        "{%0,%1,%2,%3}, {%4,%5,%6,%7}, {%8,%9}, {%0,%1,%2,%3};"
        : "+f"(d[0]), "+f"(d[1]), "+f"(d[2]), "+f"(d[3])
        : "r"(a[0]), "r"(a[1]), "r"(a[2]), "r"(a[3]), "r"(b[0]), "r"(b[1]));
}

// ---------------------------------------------------------------------------
// transpose_We: g_WeT[h][k] = We[k][h]
// ---------------------------------------------------------------------------
__global__ void transpose_We(const float* __restrict__ We) {
    int h = blockIdx.x, k = threadIdx.x;
    g_WeT[h * HH + k] = We[k * HH + h];
}

// ---------------------------------------------------------------------------
// linear_kernel (proven R1): out[r][h] = sum_k x[r][k]*W[k][h] + bias[h]
// ---------------------------------------------------------------------------
__global__ __launch_bounds__(256) void linear_kernel(
    const float* __restrict__ x, const float* __restrict__ W,
    const float* __restrict__ bias, int which)
{
    __shared__ float x_s[32 * HH];
    const int t = threadIdx.x, hq = t & 31, rg = t >> 5;
    const int row0 = blockIdx.x * 32;
    {
        const float4* xg = (const float4*)(x + (size_t)row0 * HH);
        float4* xs4 = (float4*)x_s;
        #pragma unroll
        for (int i = 0; i < 4; i++) xs4[t + i * 256] = xg[t + i * 256];
    }
    __syncthreads();
    float acc[4][4];
    #pragma unroll
    for (int r = 0; r < 4; r++)
        #pragma unroll
        for (int j = 0; j < 4; j++) acc[r][j] = 0.f;
    #pragma unroll 4
    for (int k = 0; k < HH; k++) {
        const float4 w4 = *(const float4*)(W + (size_t)k * HH + hq * 4);
        #pragma unroll
        for (int r = 0; r < 4; r++) {
            const float xv = x_s[(rg * 4 + r) * HH + k];
            acc[r][0] += xv * w4.x; acc[r][1] += xv * w4.y;
            acc[r][2] += xv * w4.z; acc[r][3] += xv * w4.w;
        }
    }
    float* out = which ? g_Vx : g_Ux;
    const float4 b4 = *(const float4*)(bias + hq * 4);
    #pragma unroll
    for (int r = 0; r < 4; r++) {
        float4 o;
        o.x = acc[r][0] + b4.x; o.y = acc[r][1] + b4.y;
        o.z = acc[r][2] + b4.z; o.w = acc[r][3] + b4.w;
        *(float4*)(out + (size_t)(row0 + rg * 4 + r) * HH + hq * 4) = o;
    }
}

// ---------------------------------------------------------------------------
// gemm_fused: one CTA per 8 nodes (grid=2000), 256 threads (8 warps).
//   D[m=h][n=edge] = WeT @ e_tile^T via mma.sync m16n8k8 tf32.
//   Warp tile: 32 (M) x 80 (N). A/B fragments via scalar LDS (stride-132 pad).
//   D -> smem (reusing B region), then epilogue: softmax over 20 cols per
//   (h, node), Vx gather, Ux add.  (be dropped: softmax shift-invariant.)
// ---------------------------------------------------------------------------
__global__ __launch_bounds__(256) void gemm_fused(
    const float* __restrict__ e,
    const int* __restrict__ edge_index,
    float* __restrict__ out)
{
    extern __shared__ __align__(16) char smem[];
    uint32_t* As = (uint32_t*)(smem + SM_A);
    uint32_t* Bs = (uint32_t*)(smem + SM_B);
    float*    Ds = (float*)(smem + SM_B);     // reuses B region after MMA
    int*      idx_s = (int*)(smem + SM_IDX);

    const int t    = threadIdx.x;
    const int lane = t & 31;
    const int wid  = t >> 5;
    const int gid  = lane >> 2;   // 0..7
    const int tid4 = lane & 3;    // 0..3
    const int node0 = blockIdx.x * NODES_PER_CTA;

    // Fill A: g_WeT [128][128] -> As[m][k] tf32 (coalesced float4 reads)
    {
        const float4* src = (const float4*)g_WeT;
        #pragma unroll
        for (int it = 0; it < 16; it++) {
            int i = t + it * 256;            // 4096 float4s
            int m = i >> 5, k4 = (i & 31) * 4;
            float4 v = src[i];
            uint4 w = make_uint4(to_tf32(v.x), to_tf32(v.y), to_tf32(v.z), to_tf32(v.w));
            *(uint4*)(As + m * AS + k4) = w;
        }
    }
    // Fill B: e rows [160][128] (contiguous in gmem) -> Bs[n][k] tf32
    {
        const float4* src = (const float4*)(e + (size_t)node0 * EE * HH);
        #pragma unroll
        for (int it = 0; it < 20; it++) {
            int i = t + it * 256;            // 5120 float4s
            int n = i >> 5, k4 = (i & 31) * 4;
            float4 v = src[i];
            uint4 w = make_uint4(to_tf32(v.x), to_tf32(v.y), to_tf32(v.z), to_tf32(v.w));
            *(uint4*)(Bs + n * BS + k4) = w;
        }
    }
    if (t < NTILE) idx_s[t] = edge_index[(size_t)node0 * EE + t];
    __syncthreads();

    // Warp tile origin
    const int m0 = (wid & 3) * 32;    // 4 warps over M=128
    const int n0 = (wid >> 2) * 80;   // 2 warps over N=160

    float d[2][10][4];
    #pragma unroll
    for (int mt = 0; mt < 2; mt++)
        #pragma unroll
        for (int j = 0; j < 10; j++)
            #pragma unroll
            for (int c = 0; c < 4; c++) d[mt][j][c] = 0.f;

    #pragma unroll 1
    for (int ks = 0; ks < 16; ks++) {
        const int k0 = ks * 8;
        uint32_t a[2][4];
        #pragma unroll
        for (int mt = 0; mt < 2; mt++) {
            const uint32_t* ap = As + (m0 + mt * 16 + gid) * AS + k0 + tid4;
            a[mt][0] = ap[0];
            a[mt][1] = ap[8 * AS];
            a[mt][2] = ap[4];
            a[mt][3] = ap[8 * AS + 4];
        }
        uint32_t b[10][2];
        #pragma unroll
        for (int j = 0; j < 10; j++) {
            const uint32_t* bp = Bs + (n0 + 8 * j + gid) * BS + k0 + tid4;
            b[j][0] = bp[0];
            b[j][1] = bp[4];
        }
        #pragma unroll
        for (int mt = 0; mt < 2; mt++)
            #pragma unroll
            for (int j = 0; j < 10; j++)
                mma_tf32(d[mt][j], a[mt], b[j]);
    }

    __syncthreads();   // everyone done reading Bs before overwriting with D

    // Store D fragments -> Ds[h][n] (row-major, stride DS)
    #pragma unroll
    for (int mt = 0; mt < 2; mt++) {
        const int row = m0 + mt * 16 + gid;
        #pragma unroll
        for (int j = 0; j < 10; j++) {
            const int col = n0 + 8 * j + 2 * tid4;
            *(float2*)(Ds + row * DS + col)       = make_float2(d[mt][j][0], d[mt][j][1]);
            *(float2*)(Ds + (row + 8) * DS + col) = make_float2(d[mt][j][2], d[mt][j][3]);
        }
    }
    __syncthreads();

    // Epilogue: 1024 (h, node) tasks over 256 threads
    #pragma unroll
    for (int it = 0; it < 4; it++) {
        const int task = it * 256 + t;
        const int g = task >> 7;          // node in tile 0..7
        const int h = task & 127;         // channel

        const float4* vp = (const float4*)(Ds + h * DS + g * EE);
        float v[EE];
        #pragma unroll
        for (int c = 0; c < 5; c++) {
            float4 q = vp[c];
            v[4 * c] = q.x; v[4 * c + 1] = q.y; v[4 * c + 2] = q.z; v[4 * c + 3] = q.w;
        }

        float m = v[0];
        #pragma unroll
        for (int i = 1; i < EE; i++) m = fmaxf(m, v[i]);
        float s = 0.f;
        #pragma unroll
        for (int i = 0; i < EE; i++) { v[i] = __expf(v[i] - m); s += v[i]; }
        const float inv = 1.f / s;

        const int node = node0 + g;
        const int b = node / NN;
        const float* vxb = g_Vx + (size_t)b * NN * HH + h;
        float acc = 0.f;
        #pragma unroll
        for (int i = 0; i < EE; i++)
            acc += v[i] * vxb[(size_t)idx_s[g * EE + i] * HH];

        out[(size_t)node * HH + h] = g_Ux[(size_t)node * HH + h] + acc * inv;
    }
}

// ---------------------------------------------------------------------------
// Launch. Inputs: x, e, Wu, bu, Wv, bv, We, be, edge_index, n_edges
// ---------------------------------------------------------------------------
extern "C" void kernel_launch(void* const* d_in, const int* in_sizes, int n_in,
                              void* d_out, int out_size)
{
    const float* x   = (const float*)d_in[0];
    const float* e   = (const float*)d_in[1];
    const float* Wu  = (const float*)d_in[2];
    const float* bu  = (const float*)d_in[3];
    const float* Wv  = (const float*)d_in[4];
    const float* bv  = (const float*)d_in[5];
    const float* We  = (const float*)d_in[6];
    // be (d_in[7]) irrelevant: softmax over E is shift-invariant per (n,h).
    const int* edge_index = (const int*)d_in[8];
    float* out = (float*)d_out;

    (void)in_sizes; (void)n_in; (void)out_size;

    // Idempotent, called every launch (no static call-count guards).
    cudaFuncSetAttribute(gemm_fused,
                         cudaFuncAttributeMaxDynamicSharedMemorySize, SM_TOTAL);

    transpose_We<<<HH, HH>>>(We);
    linear_kernel<<<ROWS / 32, 256>>>(x, Wu, bu, 0);   // Ux
    linear_kernel<<<ROWS / 32, 256>>>(x, Wv, bv, 1);   // Vx
    gemm_fused<<<ROWS / NODES_PER_CTA, 256, SM_TOTAL>>>(e, edge_index, out);
}

// round 8
// speedup vs baseline: 3.6915x; 1.2406x over previous
#include <cuda_runtime.h>
#include <cstdint>

// Problem shape (fixed by setup_inputs)
#define BB 8
#define NN 2000
#define EE 20
#define HH 128
#define ROWS (BB * NN)        // 16000 node rows
#define NODES_PER_CTA 8
#define NTILE (NODES_PER_CTA * EE)   // 160 edge rows per CTA (MMA N)

#define BS 132     // B smem stride (words): [160][128] tf32, padded
#define DS 164     // D smem stride (words): [128][160] f32, 16B multiple

// smem layout (bytes)
#define SM_IDX   0
#define SM_B     1024
#define B_BYTES  (NTILE * BS * 4)        // 84480
#define SM_TOTAL (SM_B + B_BYTES)        // 85504 -> 2 CTAs/SM
// D reuses B region: 128*164*4 = 83968 <= 84480

// Scratch (static device arrays — no runtime allocation)
__device__ float g_Ux[ROWS * HH];
__device__ float g_Vx[ROWS * HH];
// A operand pre-packed as m16n8k8 fragments, tf32 bits:
// [kstep(16)][mtile(8)][lane(32)] -> uint4 {a0,a1,a2,a3}
__device__ uint4 g_WeFrag[16 * 8 * 32];

__device__ __forceinline__ uint32_t to_tf32(float f) {
    uint32_t r; asm("cvt.rna.tf32.f32 %0, %1;" : "=r"(r) : "f"(f)); return r;
}

// m16n8k8 tf32 warp MMA (family-portable PTX; tcgen05 unavailable on sm_103 base)
__device__ __forceinline__ void mma_tf32(float d[4], const uint32_t a[4],
                                         const uint32_t b[2]) {
    asm volatile(
        "mma.sync.aligned.m16n8k8.row.col.f32.tf32.tf32.f32 "
        "{%0,%1,%2,%3}, {%4,%5,%6,%7}, {%8,%9}, {%0,%1,%2,%3};"
        : "+f"(d[0]), "+f"(d[1]), "+f"(d[2]), "+f"(d[3])
        : "r"(a[0]), "r"(a[1]), "r"(a[2]), "r"(a[3]), "r"(b[0]), "r"(b[1]));
}

// ---------------------------------------------------------------------------
// build_WeFrag: pack A[m=h][k] = We[k][m] into fragment order.
// grid = 128 (kstep*8 + mtile), block = 32 (lane).
// Fragment a0..a3 = (row gid, k t4), (row gid+8, k t4), (gid, t4+4), (gid+8, t4+4)
// ---------------------------------------------------------------------------
__global__ void build_WeFrag(const float* __restrict__ We) {
    const int blk   = blockIdx.x;       // s*8 + mtile
    const int s     = blk >> 3;
    const int mtile = blk & 7;
    const int lane  = threadIdx.x;
    const int gid   = lane >> 2, t4 = lane & 3;
    const int m  = mtile * 16 + gid;
    const int k  = s * 8 + t4;
    uint4 w;
    w.x = to_tf32(We[(size_t)k * HH + m]);
    w.y = to_tf32(We[(size_t)k * HH + m + 8]);
    w.z = to_tf32(We[(size_t)(k + 4) * HH + m]);
    w.w = to_tf32(We[(size_t)(k + 4) * HH + m + 8]);
    g_WeFrag[blk * 32 + lane] = w;
}

// ---------------------------------------------------------------------------
// linear_dual: Ux = x@Wu+bu AND Vx = x@Wv+bv in one pass (one x-tile load).
// Block: 256 threads, 32 rows. Thread tile: 4 rows x 4 cols, scalar FFMA.
// ---------------------------------------------------------------------------
__global__ __launch_bounds__(256) void linear_dual(
    const float* __restrict__ x,
    const float* __restrict__ Wu, const float* __restrict__ bu,
    const float* __restrict__ Wv, const float* __restrict__ bv)
{
    __shared__ float x_s[32 * HH];
    const int t = threadIdx.x, hq = t & 31, rg = t >> 5;
    const int row0 = blockIdx.x * 32;
    {
        const float4* xg = (const float4*)(x + (size_t)row0 * HH);
        float4* xs4 = (float4*)x_s;
        #pragma unroll
        for (int i = 0; i < 4; i++) xs4[t + i * 256] = xg[t + i * 256];
    }
    __syncthreads();
    float au[4][4], av[4][4];
    #pragma unroll
    for (int r = 0; r < 4; r++)
        #pragma unroll
        for (int j = 0; j < 4; j++) { au[r][j] = 0.f; av[r][j] = 0.f; }
    #pragma unroll 4
    for (int k = 0; k < HH; k++) {
        const float4 wu4 = *(const float4*)(Wu + (size_t)k * HH + hq * 4);
        const float4 wv4 = *(const float4*)(Wv + (size_t)k * HH + hq * 4);
        #pragma unroll
        for (int r = 0; r < 4; r++) {
            const float xv = x_s[(rg * 4 + r) * HH + k];
            au[r][0] += xv * wu4.x; au[r][1] += xv * wu4.y;
            au[r][2] += xv * wu4.z; au[r][3] += xv * wu4.w;
            av[r][0] += xv * wv4.x; av[r][1] += xv * wv4.y;
            av[r][2] += xv * wv4.z; av[r][3] += xv * wv4.w;
        }
    }
    const float4 bu4 = *(const float4*)(bu + hq * 4);
    const float4 bv4 = *(const float4*)(bv + hq * 4);
    #pragma unroll
    for (int r = 0; r < 4; r++) {
        const size_t o = (size_t)(row0 + rg * 4 + r) * HH + hq * 4;
        *(float4*)(g_Ux + o) = make_float4(au[r][0] + bu4.x, au[r][1] + bu4.y,
                                           au[r][2] + bu4.z, au[r][3] + bu4.w);
        *(float4*)(g_Vx + o) = make_float4(av[r][0] + bv4.x, av[r][1] + bv4.y,
                                           av[r][2] + bv4.z, av[r][3] + bv4.w);
    }
}

// ---------------------------------------------------------------------------
// gemm_fused: one CTA per 8 nodes (grid=2000), 256 threads (8 warps), 2 CTAs/SM.
//   D[m=h][n=edge] = We^T @ e_tile^T via mma.sync m16n8k8 tf32.
//   A fragments: direct LDG.128 from g_WeFrag (L1-resident, no smem).
//   B: e rows in smem (padded stride). D -> smem (reuses B), then epilogue:
//   softmax over 20 cols per (h,node), Vx gather, Ux add. (be dropped:
//   softmax over E is shift-invariant.)
// ---------------------------------------------------------------------------
__global__ __launch_bounds__(256, 2) void gemm_fused(
    const float* __restrict__ e,
    const int* __restrict__ edge_index,
    float* __restrict__ out)
{
    extern __shared__ __align__(16) char smem[];
    uint32_t* Bs = (uint32_t*)(smem + SM_B);
    float*    Ds = (float*)(smem + SM_B);     // reuses B region after MMA
    int*      idx_s = (int*)(smem + SM_IDX);

    const int t    = threadIdx.x;
    const int lane = t & 31;
    const int wid  = t >> 5;
    const int gid  = lane >> 2;   // 0..7
    const int tid4 = lane & 3;    // 0..3
    const int node0 = blockIdx.x * NODES_PER_CTA;

    // Fill B: e rows [160][128] (contiguous in gmem) -> Bs[n][k] tf32
    {
        const float4* src = (const float4*)(e + (size_t)node0 * EE * HH);
        #pragma unroll
        for (int it = 0; it < 20; it++) {
            int i = t + it * 256;            // 5120 float4s
            int n = i >> 5, k4 = (i & 31) * 4;
            float4 v = src[i];
            uint4 w = make_uint4(to_tf32(v.x), to_tf32(v.y), to_tf32(v.z), to_tf32(v.w));
            *(uint4*)(Bs + n * BS + k4) = w;
        }
    }
    if (t < NTILE) idx_s[t] = edge_index[(size_t)node0 * EE + t];
    __syncthreads();

    // Warp tile: 4 warps over M=128 (32 each), 2 warps over N=160 (80 each)
    const int m0 = (wid & 3) * 32;
    const int n0 = (wid >> 2) * 80;
    const int mtile0 = (wid & 3) * 2;   // fragment mtile index base

    float d[2][10][4];
    #pragma unroll
    for (int mt = 0; mt < 2; mt++)
        #pragma unroll
        for (int j = 0; j < 10; j++)
            #pragma unroll
            for (int c = 0; c < 4; c++) d[mt][j][c] = 0.f;

    #pragma unroll 1
    for (int ks = 0; ks < 16; ks++) {
        const int k0 = ks * 8;
        uint32_t a[2][4];
        #pragma unroll
        for (int mt = 0; mt < 2; mt++) {
            const uint4 af = g_WeFrag[(ks * 8 + mtile0 + mt) * 32 + lane];
            a[mt][0] = af.x; a[mt][1] = af.y; a[mt][2] = af.z; a[mt][3] = af.w;
        }
        uint32_t b[10][2];
        #pragma unroll
        for (int j = 0; j < 10; j++) {
            const uint32_t* bp = Bs + (n0 + 8 * j + gid) * BS + k0 + tid4;
            b[j][0] = bp[0];
            b[j][1] = bp[4];
        }
        #pragma unroll
        for (int mt = 0; mt < 2; mt++)
            #pragma unroll
            for (int j = 0; j < 10; j++)
                mma_tf32(d[mt][j], a[mt], b[j]);
    }

    __syncthreads();   // everyone done reading Bs before overwriting with D

    // Store D fragments -> Ds[h][n] (row-major, stride DS)
    #pragma unroll
    for (int mt = 0; mt < 2; mt++) {
        const int row = m0 + mt * 16 + gid;
        #pragma unroll
        for (int j = 0; j < 10; j++) {
            const int col = n0 + 8 * j + 2 * tid4;
            *(float2*)(Ds + row * DS + col)       = make_float2(d[mt][j][0], d[mt][j][1]);
            *(float2*)(Ds + (row + 8) * DS + col) = make_float2(d[mt][j][2], d[mt][j][3]);
        }
    }
    __syncthreads();

    // Epilogue: 1024 (h, node) tasks over 256 threads
    #pragma unroll
    for (int it = 0; it < 4; it++) {
        const int task = it * 256 + t;
        const int g = task >> 7;          // node in tile 0..7
        const int h = task & 127;         // channel

        const float4* vp = (const float4*)(Ds + h * DS + g * EE);
        float v[EE];
        #pragma unroll
        for (int c = 0; c < 5; c++) {
            float4 q = vp[c];
            v[4 * c] = q.x; v[4 * c + 1] = q.y; v[4 * c + 2] = q.z; v[4 * c + 3] = q.w;
        }

        float m = v[0];
        #pragma unroll
        for (int i = 1; i < EE; i++) m = fmaxf(m, v[i]);
        float s = 0.f;
        #pragma unroll
        for (int i = 0; i < EE; i++) { v[i] = __expf(v[i] - m); s += v[i]; }
        const float inv = 1.f / s;

        const int node = node0 + g;
        const int b = node / NN;
        const float* vxb = g_Vx + (size_t)b * NN * HH + h;
        float acc = 0.f;
        #pragma unroll
        for (int i = 0; i < EE; i++)
            acc += v[i] * vxb[(size_t)idx_s[g * EE + i] * HH];

        out[(size_t)node * HH + h] = g_Ux[(size_t)node * HH + h] + acc * inv;
    }
}

// ---------------------------------------------------------------------------
// Launch. Inputs: x, e, Wu, bu, Wv, bv, We, be, edge_index, n_edges
// ---------------------------------------------------------------------------
extern "C" void kernel_launch(void* const* d_in, const int* in_sizes, int n_in,
                              void* d_out, int out_size)
{
    const float* x   = (const float*)d_in[0];
    const float* e   = (const float*)d_in[1];
    const float* Wu  = (const float*)d_in[2];
    const float* bu  = (const float*)d_in[3];
    const float* Wv  = (const float*)d_in[4];
    const float* bv  = (const float*)d_in[5];
    const float* We  = (const float*)d_in[6];
    // be (d_in[7]) irrelevant: softmax over E is shift-invariant per (n,h).
    const int* edge_index = (const int*)d_in[8];
    float* out = (float*)d_out;

    (void)in_sizes; (void)n_in; (void)out_size;

    // Idempotent, called every launch (no call-count guards).
    cudaFuncSetAttribute(gemm_fused,
                         cudaFuncAttributeMaxDynamicSharedMemorySize, SM_TOTAL);

    build_WeFrag<<<128, 32>>>(We);
    linear_dual<<<ROWS / 32, 256>>>(x, Wu, bu, Wv, bv);
    gemm_fused<<<ROWS / NODES_PER_CTA, 256, SM_TOTAL>>>(e, edge_index, out);
}

// round 12
// speedup vs baseline: 4.4802x; 1.2137x over previous
#include <cuda_runtime.h>
#include <cstdint>

// Problem shape (fixed by setup_inputs)
#define BB 8
#define NN 2000
#define EE 20
#define HH 128
#define ROWS (BB * NN)        // 16000 node rows
#define NODES_PER_CTA 8
#define NTILE (NODES_PER_CTA * EE)   // 160 edge rows per CTA (MMA N)

// B smem: uint2 pairs {B[n][ks*8+t4], B[n][ks*8+t4+4]}, row stride 68 uint2.
// gid (row) stride 68 -> 68 mod 16 = 4: each 16-lane LDS.64 phase hits 16
// distinct 8B bank-pairs -> conflict-free fragment loads.
#define BP2 68
#define DS  164    // D smem stride (words): [128][160] f32

// smem layout (bytes) for gemm_fused
#define SM_IDX   0
#define SM_B     1024
#define B_BYTES  (NTILE * BP2 * 8)       // 87040
#define SM_TOTAL (SM_B + B_BYTES)        // 88064 -> 2 CTAs/SM
// D reuses B region: 128*164*4 = 83968 <= 87040

// Scratch (static device arrays — no runtime allocation)
__device__ float g_Ux[ROWS * HH];
__device__ float g_Vx[ROWS * HH];
// We as A-fragments: [kstep16][mtile8][lane32] uint4 {a0,a1,a2,a3}
__device__ uint4 g_WeFrag[16 * 8 * 32];
// Wu/Wv as B-fragments: [mat2][kstep16][ntile16][lane32] uint2 {b0,b1}
__device__ uint2 g_WFrag[2 * 16 * 16 * 32];

__device__ __forceinline__ uint32_t to_tf32(float f) {
    uint32_t r; asm("cvt.rna.tf32.f32 %0, %1;" : "=r"(r) : "f"(f)); return r;
}

// m16n8k8 tf32 warp MMA (family-portable; tcgen05 unavailable on sm_103 base)
__device__ __forceinline__ void mma_tf32(float d[4], const uint32_t a[4],
                                         const uint32_t b[2]) {
    asm volatile(
        "mma.sync.aligned.m16n8k8.row.col.f32.tf32.tf32.f32 "
        "{%0,%1,%2,%3}, {%4,%5,%6,%7}, {%8,%9}, {%0,%1,%2,%3};"
        : "+f"(d[0]), "+f"(d[1]), "+f"(d[2]), "+f"(d[3])
        : "r"(a[0]), "r"(a[1]), "r"(a[2]), "r"(a[3]), "r"(b[0]), "r"(b[1]));
}

// ---------------------------------------------------------------------------
// build_frags: one kernel builds all three fragment tables.
//  ids [0,4096):        WeFrag  (A-order, a = We[k][m])
//  ids [4096,12288):    WuFrag  (B-order, b = Wu[k][n])
//  ids [12288,20480):   WvFrag
// ---------------------------------------------------------------------------
__global__ void build_frags(const float* __restrict__ We,
                            const float* __restrict__ Wu,
                            const float* __restrict__ Wv)
{
    const int id = blockIdx.x * 256 + threadIdx.x;   // grid 80 x 256 = 20480
    const int lane = id & 31;
    const int gid = lane >> 2, t4 = lane & 3;
    if (id < 4096) {
        const int blk = id >> 5;          // ks*8 + mtile
        const int s = blk >> 3, mtile = blk & 7;
        const int m = mtile * 16 + gid;
        const int k = s * 8 + t4;
        uint4 w;
        w.x = to_tf32(We[(size_t)k * HH + m]);
        w.y = to_tf32(We[(size_t)k * HH + m + 8]);
        w.z = to_tf32(We[(size_t)(k + 4) * HH + m]);
        w.w = to_tf32(We[(size_t)(k + 4) * HH + m + 8]);
        g_WeFrag[blk * 32 + lane] = w;
    } else {
        const int mat = (id < 12288) ? 0 : 1;
        const float* W = mat ? Wv : Wu;
        const int idx = id - 4096 - mat * 8192;   // (ks*16+nt)*32 + lane
        const int blk = idx >> 5;                 // ks*16 + nt
        const int ks = blk >> 4, nt = blk & 15;
        const int n = nt * 8 + gid;
        const int k = ks * 8 + t4;
        uint2 w;
        w.x = to_tf32(W[(size_t)k * HH + n]);
        w.y = to_tf32(W[(size_t)(k + 4) * HH + n]);
        g_WFrag[mat * 8192 + blk * 32 + lane] = w;
    }
}

// ---------------------------------------------------------------------------
// linear_mma: Ux = x@Wu+bu AND Vx = x@Wv+bv via m16n8k8 tf32.
// Grid 250 (64 rows/CTA), 256 threads (8 warps): warp = (mat = wid>>2,
// mtile = wid&3). x tile in smem as conflict-free (k,k+4) uint2 pairs.
// W fragments stream from g_WFrag (L1-resident, coalesced LDG.64).
// ---------------------------------------------------------------------------
__global__ __launch_bounds__(256, 2) void linear_mma(
    const float* __restrict__ x,
    const float* __restrict__ bu, const float* __restrict__ bv)
{
    __shared__ __align__(16) uint2 xs2[64 * BP2];   // 34816 B

    const int t = threadIdx.x;
    const int lane = t & 31;
    const int wid = t >> 5;
    const int gid = lane >> 2, t4 = lane & 3;
    const int row0 = blockIdx.x * 64;

    // Fill x tile as pairs (rna tf32): 2048 float4s, 8 per thread
    {
        uint32_t* xw = (uint32_t*)xs2;
        const float4* src = (const float4*)(x + (size_t)row0 * HH);
        #pragma unroll
        for (int it = 0; it < 8; it++) {
            int i = t + it * 256;
            int r = i >> 5, q = i & 31;
            int ks = q >> 1, half = q & 1;
            float4 v = src[i];
            uint32_t* p = xw + r * (BP2 * 2) + ks * 8 + half;
            p[0] = to_tf32(v.x); p[2] = to_tf32(v.y);
            p[4] = to_tf32(v.z); p[6] = to_tf32(v.w);
        }
    }
    __syncthreads();

    const int mat = wid >> 2;
    const int m0 = (wid & 3) * 16;

    float d[16][4];
    #pragma unroll
    for (int nt = 0; nt < 16; nt++)
        #pragma unroll
        for (int c = 0; c < 4; c++) d[nt][c] = 0.f;

    const uint2* wf_base = g_WFrag + mat * 8192 + lane;

    #pragma unroll 1
    for (int ks = 0; ks < 16; ks++) {
        uint2 aA = xs2[(m0 + gid) * BP2 + ks * 4 + t4];
        uint2 aB = xs2[(m0 + 8 + gid) * BP2 + ks * 4 + t4];
        uint32_t a[4] = {aA.x, aB.x, aA.y, aB.y};
        const uint2* wf = wf_base + (size_t)ks * 16 * 32;
        uint32_t b[16][2];
        #pragma unroll
        for (int nt = 0; nt < 16; nt++) {
            uint2 bb = wf[nt * 32];
            b[nt][0] = bb.x; b[nt][1] = bb.y;
        }
        #pragma unroll
        for (int nt = 0; nt < 16; nt++)
            mma_tf32(d[nt], a, b[nt]);
    }

    float* out = mat ? g_Vx : g_Ux;
    const float* bias = mat ? bv : bu;
    const int r0 = row0 + m0 + gid;
    #pragma unroll
    for (int nt = 0; nt < 16; nt++) {
        const int col = nt * 8 + t4 * 2;
        const float2 b2 = *(const float2*)(bias + col);
        *(float2*)(out + (size_t)r0 * HH + col) =
            make_float2(d[nt][0] + b2.x, d[nt][1] + b2.y);
        *(float2*)(out + (size_t)(r0 + 8) * HH + col) =
            make_float2(d[nt][2] + b2.x, d[nt][3] + b2.y);
    }
}

// ---------------------------------------------------------------------------
// gemm_fused: one CTA per 8 nodes (grid=2000), 256 threads, 2 CTAs/SM.
//   D[m=h][n=edge] = We^T @ e_tile^T via m16n8k8 tf32.
//   A fragments: LDG.128 from g_WeFrag (L1-resident).
//   B: (k,k+4) uint2 pairs in smem, stride 68 -> conflict-free LDS.64 frags.
//   D -> smem (reuses B), epilogue: softmax over 20 cols per (h,node),
//   Vx gather, Ux add. (be dropped: softmax over E is shift-invariant.)
// ---------------------------------------------------------------------------
__global__ __launch_bounds__(256, 2) void gemm_fused(
    const float* __restrict__ e,
    const int* __restrict__ edge_index,
    float* __restrict__ out)
{
    extern __shared__ __align__(16) char smem[];
    uint2* Bs2 = (uint2*)(smem + SM_B);
    uint32_t* Bw = (uint32_t*)(smem + SM_B);
    float* Ds = (float*)(smem + SM_B);       // reuses B region after MMA
    int* idx_s = (int*)(smem + SM_IDX);

    const int t = threadIdx.x;
    const int lane = t & 31;
    const int wid = t >> 5;
    const int gid = lane >> 2, t4 = lane & 3;
    const int node0 = blockIdx.x * NODES_PER_CTA;

    // Fill B as pairs (rna tf32): 5120 float4s, 20 per thread
    {
        const float4* src = (const float4*)(e + (size_t)node0 * EE * HH);
        #pragma unroll
        for (int it = 0; it < 20; it++) {
            int i = t + it * 256;
            int n = i >> 5, q = i & 31;
            int ks = q >> 1, half = q & 1;
            float4 v = src[i];
            uint32_t* p = Bw + n * (BP2 * 2) + ks * 8 + half;
            p[0] = to_tf32(v.x); p[2] = to_tf32(v.y);
            p[4] = to_tf32(v.z); p[6] = to_tf32(v.w);
        }
    }
    if (t < NTILE) idx_s[t] = edge_index[(size_t)node0 * EE + t];
    __syncthreads();

    // Warp tile: 4 warps over M=128 (32 each), 2 warps over N=160 (80 each)
    const int m0 = (wid & 3) * 32;
    const int n0 = (wid >> 2) * 80;
    const int mtile0 = (wid & 3) * 2;

    float d[2][10][4];
    #pragma unroll
    for (int mt = 0; mt < 2; mt++)
        #pragma unroll
        for (int j = 0; j < 10; j++)
            #pragma unroll
            for (int c = 0; c < 4; c++) d[mt][j][c] = 0.f;

    #pragma unroll 1
    for (int ks = 0; ks < 16; ks++) {
        uint32_t a[2][4];
        #pragma unroll
        for (int mt = 0; mt < 2; mt++) {
            const uint4 af = g_WeFrag[(ks * 8 + mtile0 + mt) * 32 + lane];
            a[mt][0] = af.x; a[mt][1] = af.y; a[mt][2] = af.z; a[mt][3] = af.w;
        }
        const uint2* brow = Bs2 + (n0 + gid) * BP2 + ks * 4 + t4;
        uint32_t b[10][2];
        #pragma unroll
        for (int j = 0; j < 10; j++) {
            uint2 bb = brow[j * 8 * BP2];
            b[j][0] = bb.x; b[j][1] = bb.y;
        }
        #pragma unroll
        for (int mt = 0; mt < 2; mt++)
            #pragma unroll
            for (int j = 0; j < 10; j++)
                mma_tf32(d[mt][j], a[mt], b[j]);
    }

    __syncthreads();   // everyone done reading Bs2 before overwriting with D

    // Store D fragments -> Ds[h][n] (row-major, stride DS)
    #pragma unroll
    for (int mt = 0; mt < 2; mt++) {
        const int row = m0 + mt * 16 + gid;
        #pragma unroll
        for (int j = 0; j < 10; j++) {
            const int col = n0 + 8 * j + 2 * t4;
            *(float2*)(Ds + row * DS + col)       = make_float2(d[mt][j][0], d[mt][j][1]);
            *(float2*)(Ds + (row + 8) * DS + col) = make_float2(d[mt][j][2], d[mt][j][3]);
        }
    }
    __syncthreads();

    // Epilogue: 1024 (h, node) tasks over 256 threads
    #pragma unroll
    for (int it = 0; it < 4; it++) {
        const int task = it * 256 + t;
        const int g = task >> 7;          // node in tile 0..7
        const int h = task & 127;         // channel

        const float4* vp = (const float4*)(Ds + h * DS + g * EE);
        float v[EE];
        #pragma unroll
        for (int c = 0; c < 5; c++) {
            float4 q = vp[c];
            v[4 * c] = q.x; v[4 * c + 1] = q.y; v[4 * c + 2] = q.z; v[4 * c + 3] = q.w;
        }

        float m = v[0];
        #pragma unroll
        for (int i = 1; i < EE; i++) m = fmaxf(m, v[i]);
        float s = 0.f;
        #pragma unroll
        for (int i = 0; i < EE; i++) { v[i] = __expf(v[i] - m); s += v[i]; }
        const float inv = 1.f / s;

        const int node = node0 + g;
        const int b = node / NN;
        const float* vxb = g_Vx + (size_t)b * NN * HH + h;
        float acc = 0.f;
        #pragma unroll
        for (int i = 0; i < EE; i++)
            acc += v[i] * vxb[(size_t)idx_s[g * EE + i] * HH];

        out[(size_t)node * HH + h] = g_Ux[(size_t)node * HH + h] + acc * inv;
    }
}

// ---------------------------------------------------------------------------
// Launch. Inputs: x, e, Wu, bu, Wv, bv, We, be, edge_index, n_edges
// ---------------------------------------------------------------------------
extern "C" void kernel_launch(void* const* d_in, const int* in_sizes, int n_in,
                              void* d_out, int out_size)
{
    const float* x   = (const float*)d_in[0];
    const float* e   = (const float*)d_in[1];
    const float* Wu  = (const float*)d_in[2];
    const float* bu  = (const float*)d_in[3];
    const float* Wv  = (const float*)d_in[4];
    const float* bv  = (const float*)d_in[5];
    const float* We  = (const float*)d_in[6];
    // be (d_in[7]) irrelevant: softmax over E is shift-invariant per (n,h).
    const int* edge_index = (const int*)d_in[8];
    float* out = (float*)d_out;

    (void)in_sizes; (void)n_in; (void)out_size;

    // Idempotent, called every launch (no call-count guards).
    cudaFuncSetAttribute(gemm_fused,
                         cudaFuncAttributeMaxDynamicSharedMemorySize, SM_TOTAL);

    build_frags<<<80, 256>>>(We, Wu, Wv);
    linear_mma<<<ROWS / 64, 256>>>(x, bu, bv);
    gemm_fused<<<ROWS / NODES_PER_CTA, 256, SM_TOTAL>>>(e, edge_index, out);
}

// round 13
// speedup vs baseline: 4.6696x; 1.0423x over previous
#include <cuda_runtime.h>
#include <cstdint>

// Problem shape (fixed by setup_inputs)
#define BB 8
#define NN 2000
#define EE 20
#define HH 128
#define ROWS (BB * NN)        // 16000 node rows
#define NODES_PER_CTA 8
#define NTILE (NODES_PER_CTA * EE)   // 160 edge rows per CTA (MMA N)

// B smem: raw fp32, row-major [n][BSW words]. BSW=132 => row stride ≡ 4 mod 32
// banks; fragment LDS.32 bank = 4*gid + t4 = lane id -> conflict-free.
#define BSW 132
#define DS  164    // D smem stride (words): [128][160] f32, 16B multiple

// smem layout (bytes) for gemm_fused
#define SM_IDX   0
#define SM_B     1024
#define B_BYTES  (NTILE * BSW * 4)       // 84480
#define SM_TOTAL (SM_B + B_BYTES)        // 85504 -> 2 CTAs/SM
// D reuses B region: 128*164*4 = 83968 <= 84480

// Scratch (static device arrays — no runtime allocation)
__device__ float g_Ux[ROWS * HH];
__device__ float g_Vx[ROWS * HH];
// We as A-fragments: [kstep16][mtile8][lane32] uint4 {a0,a1,a2,a3}
__device__ uint4 g_WeFrag[16 * 8 * 32];
// Wu/Wv as B-fragments: [mat2][kstep16][ntile16][lane32] uint2 {b0,b1}
__device__ uint2 g_WFrag[2 * 16 * 16 * 32];

__device__ __forceinline__ uint32_t to_tf32(float f) {
    uint32_t r; asm("cvt.rna.tf32.f32 %0, %1;" : "=r"(r) : "f"(f)); return r;
}

// m16n8k8 tf32 warp MMA (family-portable; tcgen05 unavailable on sm_103 base)
__device__ __forceinline__ void mma_tf32(float d[4], const uint32_t a[4],
                                         const uint32_t b[2]) {
    asm volatile(
        "mma.sync.aligned.m16n8k8.row.col.f32.tf32.tf32.f32 "
        "{%0,%1,%2,%3}, {%4,%5,%6,%7}, {%8,%9}, {%0,%1,%2,%3};"
        : "+f"(d[0]), "+f"(d[1]), "+f"(d[2]), "+f"(d[3])
        : "r"(a[0]), "r"(a[1]), "r"(a[2]), "r"(a[3]), "r"(b[0]), "r"(b[1]));
}

// cp.async 16B (LDGSTS, sm_80+ family-portable)
__device__ __forceinline__ void cp_async16(uint32_t smem_dst, const void* gsrc) {
    asm volatile("cp.async.ca.shared.global [%0], [%1], 16;"
                 :: "r"(smem_dst), "l"(gsrc) : "memory");
}
__device__ __forceinline__ void cp_async_commit_wait() {
    asm volatile("cp.async.commit_group;" ::: "memory");
    asm volatile("cp.async.wait_group 0;" ::: "memory");
}

// ---------------------------------------------------------------------------
// build_frags: one kernel builds all three fragment tables.
// ---------------------------------------------------------------------------
__global__ void build_frags(const float* __restrict__ We,
                            const float* __restrict__ Wu,
                            const float* __restrict__ Wv)
{
    const int id = blockIdx.x * 256 + threadIdx.x;   // grid 80 x 256 = 20480
    const int lane = id & 31;
    const int gid = lane >> 2, t4 = lane & 3;
    if (id < 4096) {
        const int blk = id >> 5;          // ks*8 + mtile
        const int s = blk >> 3, mtile = blk & 7;
        const int m = mtile * 16 + gid;
        const int k = s * 8 + t4;
        uint4 w;
        w.x = to_tf32(We[(size_t)k * HH + m]);
        w.y = to_tf32(We[(size_t)k * HH + m + 8]);
        w.z = to_tf32(We[(size_t)(k + 4) * HH + m]);
        w.w = to_tf32(We[(size_t)(k + 4) * HH + m + 8]);
        g_WeFrag[blk * 32 + lane] = w;
    } else {
        const int mat = (id < 12288) ? 0 : 1;
        const float* W = mat ? Wv : Wu;
        const int idx = id - 4096 - mat * 8192;   // (ks*16+nt)*32 + lane
        const int blk = idx >> 5;                 // ks*16 + nt
        const int ks = blk >> 4, nt = blk & 15;
        const int n = nt * 8 + gid;
        const int k = ks * 8 + t4;
        uint2 w;
        w.x = to_tf32(W[(size_t)k * HH + n]);
        w.y = to_tf32(W[(size_t)(k + 4) * HH + n]);
        g_WFrag[mat * 8192 + blk * 32 + lane] = w;
    }
}

// ---------------------------------------------------------------------------
// linear_mma: Ux = x@Wu+bu AND Vx = x@Wv+bv via m16n8k8 tf32.
// Grid 250 (64 rows/CTA), 256 threads: warp = (mat = wid>>2, mtile = wid&3).
// x tile in smem raw fp32, stride 132 (conflict-free); cvt in-register.
// ---------------------------------------------------------------------------
__global__ __launch_bounds__(256, 2) void linear_mma(
    const float* __restrict__ x,
    const float* __restrict__ bu, const float* __restrict__ bv)
{
    __shared__ __align__(16) uint32_t xs[64 * BSW];   // 33792 B

    const int t = threadIdx.x;
    const int lane = t & 31;
    const int wid = t >> 5;
    const int gid = lane >> 2, t4 = lane & 3;
    const int row0 = blockIdx.x * 64;

    // Async fill of x tile (raw fp32): 2048 16B chunks, 8 per thread
    {
        const float4* src = (const float4*)(x + (size_t)row0 * HH);
        const uint32_t sb = (uint32_t)__cvta_generic_to_shared(xs);
        #pragma unroll
        for (int it = 0; it < 8; it++) {
            int i = t + it * 256;
            int r = i >> 5, q = i & 31;
            cp_async16(sb + (r * BSW + q * 4) * 4, src + i);
        }
    }
    cp_async_commit_wait();
    __syncthreads();

    const int mat = wid >> 2;
    const int m0 = (wid & 3) * 16;

    float d[16][4];
    #pragma unroll
    for (int nt = 0; nt < 16; nt++)
        #pragma unroll
        for (int c = 0; c < 4; c++) d[nt][c] = 0.f;

    const uint2* wf_base = g_WFrag + mat * 8192 + lane;

    #pragma unroll 1
    for (int ks = 0; ks < 16; ks++) {
        const uint32_t* rA = xs + (m0 + gid) * BSW + ks * 8 + t4;
        const uint32_t* rB = xs + (m0 + 8 + gid) * BSW + ks * 8 + t4;
        uint32_t a[4];
        a[0] = to_tf32(__uint_as_float(rA[0]));
        a[1] = to_tf32(__uint_as_float(rB[0]));
        a[2] = to_tf32(__uint_as_float(rA[4]));
        a[3] = to_tf32(__uint_as_float(rB[4]));
        const uint2* wf = wf_base + (size_t)ks * 16 * 32;
        uint32_t b[16][2];
        #pragma unroll
        for (int nt = 0; nt < 16; nt++) {
            uint2 bb = wf[nt * 32];
            b[nt][0] = bb.x; b[nt][1] = bb.y;
        }
        #pragma unroll
        for (int nt = 0; nt < 16; nt++)
            mma_tf32(d[nt], a, b[nt]);
    }

    float* out = mat ? g_Vx : g_Ux;
    const float* bias = mat ? bv : bu;
    const int r0 = row0 + m0 + gid;
    #pragma unroll
    for (int nt = 0; nt < 16; nt++) {
        const int col = nt * 8 + t4 * 2;
        const float2 b2 = *(const float2*)(bias + col);
        *(float2*)(out + (size_t)r0 * HH + col) =
            make_float2(d[nt][0] + b2.x, d[nt][1] + b2.y);
        *(float2*)(out + (size_t)(r0 + 8) * HH + col) =
            make_float2(d[nt][2] + b2.x, d[nt][3] + b2.y);
    }
}

// ---------------------------------------------------------------------------
// gemm_fused: one CTA per 8 nodes (grid=2000), 256 threads, 2 CTAs/SM.
//   Fill: cp.async raw fp32 e rows -> smem [160][132] (fire-and-forget).
//   D[m=h][n=edge] = We^T @ e_tile^T via m16n8k8 tf32 (cvt.rna in-register).
//   A fragments: LDG.128 from g_WeFrag. B fragments: conflict-free LDS.32.
//   D -> smem (reuses B), epilogue: softmax over 20 cols per (h,node),
//   Vx gather, Ux add. (be dropped: softmax over E is shift-invariant.)
// ---------------------------------------------------------------------------
__global__ __launch_bounds__(256, 2) void gemm_fused(
    const float* __restrict__ e,
    const int* __restrict__ edge_index,
    float* __restrict__ out)
{
    extern __shared__ __align__(16) char smem[];
    uint32_t* Bw = (uint32_t*)(smem + SM_B);
    float* Ds = (float*)(smem + SM_B);       // reuses B region after MMA
    int* idx_s = (int*)(smem + SM_IDX);

    const int t = threadIdx.x;
    const int lane = t & 31;
    const int wid = t >> 5;
    const int gid = lane >> 2, t4 = lane & 3;
    const int node0 = blockIdx.x * NODES_PER_CTA;

    // Async fill of B (raw fp32): 5120 16B chunks, 20 per thread
    {
        const float4* src = (const float4*)(e + (size_t)node0 * EE * HH);
        const uint32_t sb = (uint32_t)__cvta_generic_to_shared(Bw);
        #pragma unroll
        for (int it = 0; it < 20; it++) {
            int i = t + it * 256;
            int n = i >> 5, q = i & 31;
            cp_async16(sb + (n * BSW + q * 4) * 4, src + i);
        }
    }
    if (t < NTILE) idx_s[t] = edge_index[(size_t)node0 * EE + t];
    cp_async_commit_wait();
    __syncthreads();

    // Warp tile: 4 warps over M=128 (32 each), 2 warps over N=160 (80 each)
    const int m0 = (wid & 3) * 32;
    const int n0 = (wid >> 2) * 80;
    const int mtile0 = (wid & 3) * 2;

    float d[2][10][4];
    #pragma unroll
    for (int mt = 0; mt < 2; mt++)
        #pragma unroll
        for (int j = 0; j < 10; j++)
            #pragma unroll
            for (int c = 0; c < 4; c++) d[mt][j][c] = 0.f;

    #pragma unroll 1
    for (int ks = 0; ks < 16; ks++) {
        uint32_t a[2][4];
        #pragma unroll
        for (int mt = 0; mt < 2; mt++) {
            const uint4 af = g_WeFrag[(ks * 8 + mtile0 + mt) * 32 + lane];
            a[mt][0] = af.x; a[mt][1] = af.y; a[mt][2] = af.z; a[mt][3] = af.w;
        }
        const uint32_t* brow = Bw + (n0 + gid) * BSW + ks * 8 + t4;
        uint32_t b[10][2];
        #pragma unroll
        for (int j = 0; j < 10; j++) {
            b[j][0] = to_tf32(__uint_as_float(brow[j * 8 * BSW]));
            b[j][1] = to_tf32(__uint_as_float(brow[j * 8 * BSW + 4]));
        }
        #pragma unroll
        for (int mt = 0; mt < 2; mt++)
            #pragma unroll
            for (int j = 0; j < 10; j++)
                mma_tf32(d[mt][j], a[mt], b[j]);
    }

    __syncthreads();   // everyone done reading B before overwriting with D

    // Store D fragments -> Ds[h][n] (row-major, stride DS)
    #pragma unroll
    for (int mt = 0; mt < 2; mt++) {
        const int row = m0 + mt * 16 + gid;
        #pragma unroll
        for (int j = 0; j < 10; j++) {
            const int col = n0 + 8 * j + 2 * t4;
            *(float2*)(Ds + row * DS + col)       = make_float2(d[mt][j][0], d[mt][j][1]);
            *(float2*)(Ds + (row + 8) * DS + col) = make_float2(d[mt][j][2], d[mt][j][3]);
        }
    }
    __syncthreads();

    // Epilogue: 1024 (h, node) tasks over 256 threads
    #pragma unroll
    for (int it = 0; it < 4; it++) {
        const int task = it * 256 + t;
        const int g = task >> 7;          // node in tile 0..7
        const int h = task & 127;         // channel

        const float4* vp = (const float4*)(Ds + h * DS + g * EE);
        float v[EE];
        #pragma unroll
        for (int c = 0; c < 5; c++) {
            float4 q = vp[c];
            v[4 * c] = q.x; v[4 * c + 1] = q.y; v[4 * c + 2] = q.z; v[4 * c + 3] = q.w;
        }

        float m = v[0];
        #pragma unroll
        for (int i = 1; i < EE; i++) m = fmaxf(m, v[i]);
        float s = 0.f;
        #pragma unroll
        for (int i = 0; i < EE; i++) { v[i] = __expf(v[i] - m); s += v[i]; }
        const float inv = 1.f / s;

        const int node = node0 + g;
        const int b = node / NN;
        const float* vxb = g_Vx + (size_t)b * NN * HH + h;
        float acc = 0.f;
        #pragma unroll
        for (int i = 0; i < EE; i++)
            acc += v[i] * vxb[(size_t)idx_s[g * EE + i] * HH];

        out[(size_t)node * HH + h] = g_Ux[(size_t)node * HH + h] + acc * inv;
    }
}

// ---------------------------------------------------------------------------
// Launch. Inputs: x, e, Wu, bu, Wv, bv, We, be, edge_index, n_edges
// ---------------------------------------------------------------------------
extern "C" void kernel_launch(void* const* d_in, const int* in_sizes, int n_in,
                              void* d_out, int out_size)
{
    const float* x   = (const float*)d_in[0];
    const float* e   = (const float*)d_in[1];
    const float* Wu  = (const float*)d_in[2];
    const float* bu  = (const float*)d_in[3];
    const float* Wv  = (const float*)d_in[4];
    const float* bv  = (const float*)d_in[5];
    const float* We  = (const float*)d_in[6];
    // be (d_in[7]) irrelevant: softmax over E is shift-invariant per (n,h).
    const int* edge_index = (const int*)d_in[8];
    float* out = (float*)d_out;

    (void)in_sizes; (void)n_in; (void)out_size;

    // Idempotent, called every launch (no call-count guards).
    cudaFuncSetAttribute(gemm_fused,
                         cudaFuncAttributeMaxDynamicSharedMemorySize, SM_TOTAL);

    build_frags<<<80, 256>>>(We, Wu, Wv);
    linear_mma<<<ROWS / 64, 256>>>(x, bu, bv);
    gemm_fused<<<ROWS / NODES_PER_CTA, 256, SM_TOTAL>>>(e, edge_index, out);
}